// round 6
// baseline (speedup 1.0000x reference)
#include <cuda_runtime.h>
#include <math.h>

#define NN 50000
#define NE 800000
#define NG 512
#define UF 64
#define TOT (NE + NN)

// ---------------- device scratch (no allocs allowed) ----------------
__device__ int   g_rs[2][NN + 1];     // CSR row starts (by dst)
__device__ int   g_deg[2][NN];        // in-degree incl self loop
__device__ int   g_cnt[2][NN];        // scatter cursors
__device__ int   g_col[2][TOT];       // CSR col = src
__device__ float g_dinv[2][NN];       // rsqrt(deg)
__device__ float g_als[2][NN];        // alpha_src per node
__device__ float g_ald[2][NN];        // alpha_dst per node
__device__ float g_x[2][2][NN * UF];  // ping-pong feature buffers
__device__ float g_poolS[2][NG];
__device__ float g_poolC[2][NG];

static __device__ __forceinline__ float warp_sum(float v) {
    #pragma unroll
    for (int o = 16; o; o >>= 1) v += __shfl_xor_sync(0xffffffffu, v, o);
    return v;
}
static __device__ __forceinline__ float warp_max(float v) {
    #pragma unroll
    for (int o = 16; o; o >>= 1) v = fmaxf(v, __shfl_xor_sync(0xffffffffu, v, o));
    return v;
}

// ---------------- init / CSR build ----------------
__global__ void k_init() {
    int i = blockIdx.x * blockDim.x + threadIdx.x;
    if (i < 2 * NN) {
        int br = i / NN, j = i % NN;
        g_deg[br][j] = 1;   // self loop
        g_cnt[br][j] = 0;
    }
    if (i < 2 * NG) {
        int br = i / NG, j = i % NG;
        g_poolS[br][j] = 0.f;
        g_poolC[br][j] = 0.f;
    }
}

__global__ void k_hist(const int* __restrict__ ei, int br) {
    int e = blockIdx.x * blockDim.x + threadIdx.x;
    if (e < NE) atomicAdd(&g_deg[br][ei[NE + e]], 1);
}

__global__ void k_bcount(const int* __restrict__ batch, int br) {
    int i = blockIdx.x * blockDim.x + threadIdx.x;
    if (i < NN) atomicAdd(&g_poolC[br][batch[i]], 1.0f);
}

// single block per branch; warp-scan based prefix sum of degrees
__global__ void k_scan() {
    int br = blockIdx.x;
    int* deg = g_deg[br];
    int* rs  = g_rs[br];
    __shared__ int swt[32];
    __shared__ int carry;
    int tid = threadIdx.x, lane = tid & 31, wid = tid >> 5;
    if (tid == 0) { carry = 0; rs[0] = 0; }
    __syncthreads();
    for (int base = 0; base < NN; base += 1024) {
        int i = base + tid;
        int v = (i < NN) ? deg[i] : 0;
        int sv = v;
        #pragma unroll
        for (int o = 1; o < 32; o <<= 1) {
            int t = __shfl_up_sync(0xffffffffu, sv, o);
            if (lane >= o) sv += t;
        }
        if (lane == 31) swt[wid] = sv;
        __syncthreads();
        if (wid == 0) {
            int w = swt[lane];
            #pragma unroll
            for (int o = 1; o < 32; o <<= 1) {
                int t = __shfl_up_sync(0xffffffffu, w, o);
                if (lane >= o) w += t;
            }
            swt[lane] = w;
        }
        __syncthreads();
        int off = (wid > 0) ? swt[wid - 1] : 0;
        int incl = carry + off + sv;
        if (i < NN) rs[i + 1] = incl;
        int total = swt[31];
        __syncthreads();
        if (tid == 0) carry += total;
        __syncthreads();
    }
}

__global__ void k_dinv() {
    int i = blockIdx.x * blockDim.x + threadIdx.x;
    if (i < 2 * NN) {
        int br = i / NN, j = i % NN;
        g_dinv[br][j] = rsqrtf((float)g_deg[br][j]);
    }
}

__global__ void k_scatter(const int* __restrict__ ei, int br) {
    int idx = blockIdx.x * blockDim.x + threadIdx.x;
    if (idx >= TOT) return;
    int s, d;
    if (idx < NE) { s = ei[idx]; d = ei[NE + idx]; }
    else          { s = d = idx - NE; }
    int pos = g_rs[br][d] + atomicAdd(&g_cnt[br][d], 1);
    g_col[br][pos] = s;
}

// ---------------- GAT linear: h = x @ W_gat, alpha_s/d ----------------
__global__ void __launch_bounds__(256) k_gath(
    const float* __restrict__ x, const float* __restrict__ Wg,
    const float* __restrict__ asr, const float* __restrict__ adr, int br)
{
    __shared__ float sW[9 * UF];
    __shared__ float sas[UF], sad[UF];
    for (int i = threadIdx.x; i < 9 * UF; i += 256) sW[i] = Wg[i];
    if (threadIdx.x < UF) { sas[threadIdx.x] = asr[threadIdx.x]; sad[threadIdx.x] = adr[threadIdx.x]; }
    __syncthreads();
    int gw   = (blockIdx.x * 256 + threadIdx.x) >> 5;
    int lane = threadIdx.x & 31;
    if (gw >= NN) return;
    float xr[9];
    #pragma unroll
    for (int k = 0; k < 9; k++) xr[k] = __ldg(&x[gw * 9 + k]);
    int f0 = 2 * lane;
    float h0 = 0.f, h1 = 0.f;
    #pragma unroll
    for (int k = 0; k < 9; k++) {
        h0 += xr[k] * sW[k * UF + f0];
        h1 += xr[k] * sW[k * UF + f0 + 1];
    }
    *(float2*)&g_x[br][0][gw * UF + f0] = make_float2(h0, h1);
    float ps = h0 * sas[f0] + h1 * sas[f0 + 1];
    float pd = h0 * sad[f0] + h1 * sad[f0 + 1];
    ps = warp_sum(ps);
    pd = warp_sum(pd);
    if (lane == 0) { g_als[br][gw] = ps; g_ald[br][gw] = pd; }
}

// ---------------- GAT aggregate + tanh + (x @ W_gcn0) fused ----------------
__global__ void __launch_bounds__(256) k_gat_agg(
    const float* __restrict__ bgat, const float* __restrict__ Wn, int br)
{
    __shared__ float sW[UF * UF];
    for (int i = threadIdx.x; i < UF * UF; i += 256) sW[i] = Wn[i];
    __syncthreads();
    int lane = threadIdx.x & 31;
    int wid  = (blockIdx.x * 256 + threadIdx.x) >> 5;
    int nw   = gridDim.x * 8;
    const int*   __restrict__ rs  = g_rs[br];
    const int*   __restrict__ col = g_col[br];
    const float* __restrict__ als = g_als[br];
    const float* __restrict__ hin = g_x[br][0];
    float*       __restrict__ out = g_x[br][1];
    float bg0 = __ldg(&bgat[2 * lane]);
    float bg1 = __ldg(&bgat[2 * lane + 1]);

    for (int node = wid; node < NN; node += nw) {
        int beg = rs[node], end = rs[node + 1];
        float ad = g_ald[br][node];
        // pass 1: segment max
        float m = -3.0e38f;
        for (int j = beg + lane; j < end; j += 32) {
            float e = als[col[j]] + ad;
            e = e > 0.f ? e : 0.2f * e;
            m = fmaxf(m, e);
        }
        m = warp_max(m);
        // pass 2: weighted gather
        float a0 = 0.f, a1 = 0.f, den = 0.f;
        for (int base = beg; base < end; base += 32) {
            int j = base + lane;
            float ex = 0.f; int s = 0;
            if (j < end) {
                s = col[j];
                float e = als[s] + ad;
                e = e > 0.f ? e : 0.2f * e;
                ex = __expf(e - m);
            }
            den += ex;
            int c = min(32, end - base);
            for (int k = 0; k < c; k++) {
                float exk = __shfl_sync(0xffffffffu, ex, k);
                int   sk  = __shfl_sync(0xffffffffu, s, k);
                float2 hv = *(const float2*)&hin[sk * UF + 2 * lane];
                a0 += exk * hv.x;
                a1 += exk * hv.y;
            }
        }
        den = warp_sum(den);
        float inv = 1.f / den;
        float y0 = tanhf(a0 * inv + bg0);
        float y1 = tanhf(a1 * inv + bg1);
        // fused transform by W_gcn[0]
        float o0 = 0.f, o1 = 0.f;
        #pragma unroll
        for (int k = 0; k < UF; k++) {
            float yk = __shfl_sync(0xffffffffu, (k & 1) ? y1 : y0, k >> 1);
            float2 wv = *(const float2*)&sW[k * UF + 2 * lane];
            o0 += yk * wv.x;
            o1 += yk * wv.y;
        }
        *(float2*)&out[node * UF + 2 * lane] = make_float2(o0, o1);
    }
}

// ---------------- GCN aggregate + tanh + (x @ Wnext) fused ----------------
__global__ void __launch_bounds__(256) k_gcn_agg(
    const float* __restrict__ bg, const float* __restrict__ Wn, int br)
{
    __shared__ float sW[UF * UF];
    for (int i = threadIdx.x; i < UF * UF; i += 256) sW[i] = Wn[i];
    __syncthreads();
    int lane = threadIdx.x & 31;
    int wid  = (blockIdx.x * 256 + threadIdx.x) >> 5;
    int nw   = gridDim.x * 8;
    const int*   __restrict__ rs   = g_rs[br];
    const int*   __restrict__ col  = g_col[br];
    const float* __restrict__ dinv = g_dinv[br];
    const float* __restrict__ hin  = g_x[br][1];
    float*       __restrict__ out  = g_x[br][0];
    float bg0 = __ldg(&bg[2 * lane]);
    float bg1 = __ldg(&bg[2 * lane + 1]);

    for (int node = wid; node < NN; node += nw) {
        int beg = rs[node], end = rs[node + 1];
        float di = dinv[node];
        float a0 = 0.f, a1 = 0.f;
        for (int base = beg; base < end; base += 32) {
            int j = base + lane;
            float w = 0.f; int s = 0;
            if (j < end) { s = col[j]; w = dinv[s] * di; }
            int c = min(32, end - base);
            for (int k = 0; k < c; k++) {
                float wk = __shfl_sync(0xffffffffu, w, k);
                int   sk = __shfl_sync(0xffffffffu, s, k);
                float2 hv = *(const float2*)&hin[sk * UF + 2 * lane];
                a0 += wk * hv.x;
                a1 += wk * hv.y;
            }
        }
        float y0 = tanhf(a0 + bg0);
        float y1 = tanhf(a1 + bg1);
        float o0 = 0.f, o1 = 0.f;
        #pragma unroll
        for (int k = 0; k < UF; k++) {
            float yk = __shfl_sync(0xffffffffu, (k & 1) ? y1 : y0, k >> 1);
            float2 wv = *(const float2*)&sW[k * UF + 2 * lane];
            o0 += yk * wv.x;
            o1 += yk * wv.y;
        }
        *(float2*)&out[node * UF + 2 * lane] = make_float2(o0, o1);
    }
}

// ---------- GCN2 aggregate + tanh + full MLP + mean-pool partial ----------
__global__ void __launch_bounds__(256) k_final_node(
    const float* __restrict__ bg,
    const float* __restrict__ W1, const float* __restrict__ b1,
    const float* __restrict__ W2, const float* __restrict__ b2,
    const float* __restrict__ W3, const float* __restrict__ b3,
    const int* __restrict__ batch, int br)
{
    __shared__ float sW1[UF * UF];
    __shared__ float sW2[UF * 32];
    __shared__ float sb1[UF], sb2[32], sW3[32];
    __shared__ float sb3;
    for (int i = threadIdx.x; i < UF * UF; i += 256) sW1[i] = W1[i];
    for (int i = threadIdx.x; i < UF * 32; i += 256) sW2[i] = W2[i];
    if (threadIdx.x < UF) sb1[threadIdx.x] = b1[threadIdx.x];
    if (threadIdx.x < 32) { sb2[threadIdx.x] = b2[threadIdx.x]; sW3[threadIdx.x] = W3[threadIdx.x]; }
    if (threadIdx.x == 0) sb3 = b3[0];
    __syncthreads();

    int lane = threadIdx.x & 31;
    int wid  = (blockIdx.x * 256 + threadIdx.x) >> 5;
    int nw   = gridDim.x * 8;
    const int*   __restrict__ rs   = g_rs[br];
    const int*   __restrict__ col  = g_col[br];
    const float* __restrict__ dinv = g_dinv[br];
    const float* __restrict__ hin  = g_x[br][0];
    float bg0 = __ldg(&bg[2 * lane]);
    float bg1 = __ldg(&bg[2 * lane + 1]);

    for (int node = wid; node < NN; node += nw) {
        int beg = rs[node], end = rs[node + 1];
        float di = dinv[node];
        float a0 = 0.f, a1 = 0.f;
        for (int base = beg; base < end; base += 32) {
            int j = base + lane;
            float w = 0.f; int s = 0;
            if (j < end) { s = col[j]; w = dinv[s] * di; }
            int c = min(32, end - base);
            for (int k = 0; k < c; k++) {
                float wk = __shfl_sync(0xffffffffu, w, k);
                int   sk = __shfl_sync(0xffffffffu, s, k);
                float2 hv = *(const float2*)&hin[sk * UF + 2 * lane];
                a0 += wk * hv.x;
                a1 += wk * hv.y;
            }
        }
        float y0 = tanhf(a0 + bg0);
        float y1 = tanhf(a1 + bg1);
        // MLP layer 1: 64 -> 64, tanh
        float o0 = sb1[2 * lane], o1 = sb1[2 * lane + 1];
        #pragma unroll
        for (int k = 0; k < UF; k++) {
            float yk = __shfl_sync(0xffffffffu, (k & 1) ? y1 : y0, k >> 1);
            float2 wv = *(const float2*)&sW1[k * UF + 2 * lane];
            o0 += yk * wv.x;
            o1 += yk * wv.y;
        }
        o0 = tanhf(o0);
        o1 = tanhf(o1);
        // MLP layer 2: 64 -> 32, tanh (one output per lane)
        float z = sb2[lane];
        #pragma unroll
        for (int k = 0; k < UF; k++) {
            float ok = __shfl_sync(0xffffffffu, (k & 1) ? o1 : o0, k >> 1);
            z += ok * sW2[k * 32 + lane];
        }
        z = tanhf(z);
        // MLP layer 3: 32 -> 1
        float p = z * sW3[lane];
        p = warp_sum(p);
        if (lane == 0) atomicAdd(&g_poolS[br][batch[node]], p + sb3);
    }
}

__global__ void k_out(float* __restrict__ out) {
    int g = blockIdx.x * blockDim.x + threadIdx.x;
    if (g < NG) {
        float ua = g_poolS[0][g] / fmaxf(g_poolC[0][g], 1.f);
        float ub = g_poolS[1][g] / fmaxf(g_poolC[1][g], 1.f);
        out[g] = 1.f / (1.f + expf(-(ub - ua)));
    }
}

// ---------------- launch ----------------
extern "C" void kernel_launch(void* const* d_in, const int* in_sizes, int n_in,
                              void* d_out, int out_size)
{
    const float* x_a   = (const float*)d_in[0];
    const float* x_b   = (const float*)d_in[1];
    const int*   ei_a  = (const int*)d_in[2];
    const int*   ei_b  = (const int*)d_in[3];
    const int*   ba    = (const int*)d_in[4];
    const int*   bb    = (const int*)d_in[5];
    const float* W_gat = (const float*)d_in[6];
    const float* a_src = (const float*)d_in[7];
    const float* a_dst = (const float*)d_in[8];
    const float* b_gat = (const float*)d_in[9];
    const float* W_gcn = (const float*)d_in[10];
    const float* b_gcn = (const float*)d_in[11];
    const float* W1    = (const float*)d_in[12];
    const float* b1    = (const float*)d_in[13];
    const float* W2    = (const float*)d_in[14];
    const float* b2    = (const float*)d_in[15];
    const float* W3    = (const float*)d_in[16];
    const float* b3    = (const float*)d_in[17];
    float* out = (float*)d_out;

    k_init<<<(2 * NN + 255) / 256, 256>>>();
    k_hist<<<(NE + 255) / 256, 256>>>(ei_a, 0);
    k_hist<<<(NE + 255) / 256, 256>>>(ei_b, 1);
    k_bcount<<<(NN + 255) / 256, 256>>>(ba, 0);
    k_bcount<<<(NN + 255) / 256, 256>>>(bb, 1);
    k_scan<<<2, 1024>>>();
    k_dinv<<<(2 * NN + 255) / 256, 256>>>();
    k_scatter<<<(TOT + 255) / 256, 256>>>(ei_a, 0);
    k_scatter<<<(TOT + 255) / 256, 256>>>(ei_b, 1);
    k_gath<<<(NN * 32 + 255) / 256, 256>>>(x_a, W_gat, a_src, a_dst, 0);
    k_gath<<<(NN * 32 + 255) / 256, 256>>>(x_b, W_gat, a_src, a_dst, 1);

    const int NB = 1184;
    k_gat_agg<<<NB, 256>>>(b_gat, W_gcn, 0);
    k_gat_agg<<<NB, 256>>>(b_gat, W_gcn, 1);
    k_gcn_agg<<<NB, 256>>>(b_gcn, W_gcn + UF * UF, 0);
    k_gcn_agg<<<NB, 256>>>(b_gcn, W_gcn + UF * UF, 1);
    k_final_node<<<NB, 256>>>(b_gcn + UF, W1, b1, W2, b2, W3, b3, ba, 0);
    k_final_node<<<NB, 256>>>(b_gcn + UF, W1, b1, W2, b2, W3, b3, bb, 1);
    k_out<<<(NG + 255) / 256, 256>>>(out);
}

// round 9
// speedup vs baseline: 1.1095x; 1.1095x over previous
#include <cuda_runtime.h>
#include <math.h>

#define NN 50000
#define NE 800000
#define NG 512
#define UF 64
#define TOT (NE + NN)

// ---------------- device scratch (no allocs allowed) ----------------
__device__ int   g_rs[2][NN + 1];     // CSR row starts (by dst)
__device__ int   g_deg[2][NN];        // in-degree incl self loop
__device__ int   g_cnt[2][NN];        // scatter cursors
__device__ int   g_col[2][TOT];       // CSR col = src
__device__ float g_ew[2][TOT];        // GAT edge logits e (leaky-relu'd)
__device__ float g_dinv[2][NN];       // rsqrt(deg)
__device__ float g_als[2][NN];        // alpha_src per node
__device__ float g_ald[2][NN];        // alpha_dst per node
__device__ float g_x[2][2][NN * UF];  // ping-pong feature buffers
__device__ float g_poolS[2][NG];

static __device__ __forceinline__ float warp_sum(float v) {
    #pragma unroll
    for (int o = 16; o; o >>= 1) v += __shfl_xor_sync(0xffffffffu, v, o);
    return v;
}
static __device__ __forceinline__ float warp_max(float v) {
    #pragma unroll
    for (int o = 16; o; o >>= 1) v = fmaxf(v, __shfl_xor_sync(0xffffffffu, v, o));
    return v;
}

// ---------------- launch 0: init ----------------
__global__ void k_init() {
    int i = blockIdx.x * blockDim.x + threadIdx.x;
    if (i < 2 * NN) {
        int br = i / NN, j = i % NN;
        g_deg[br][j] = 1;   // self loop
        g_cnt[br][j] = 0;
    }
    if (i < 2 * NG) {
        int br = i / NG, j = i % NG;
        g_poolS[br][j] = 0.f;
    }
}

// ---------------- launch 1: degree histogram (both branches) ----------------
__global__ void k_hist(const int* __restrict__ ei_a, const int* __restrict__ ei_b) {
    int idx = blockIdx.x * blockDim.x + threadIdx.x;
    if (idx >= 2 * NE) return;
    int br = idx >= NE;
    int e  = idx - br * NE;
    const int* ei = br ? ei_b : ei_a;
    atomicAdd(&g_deg[br][ei[NE + e]], 1);
}

// ---------------- launch 2: prefix scan + dinv (1 block per branch) ----------------
__global__ void k_scan() {
    int br = blockIdx.x;
    int* deg = g_deg[br];
    int* rs  = g_rs[br];
    __shared__ int swt[32];
    __shared__ int carry;
    int tid = threadIdx.x, lane = tid & 31, wid = tid >> 5;
    if (tid == 0) { carry = 0; rs[0] = 0; }
    __syncthreads();
    for (int base = 0; base < NN; base += 1024) {
        int i = base + tid;
        int v = (i < NN) ? deg[i] : 0;
        int sv = v;
        #pragma unroll
        for (int o = 1; o < 32; o <<= 1) {
            int t = __shfl_up_sync(0xffffffffu, sv, o);
            if (lane >= o) sv += t;
        }
        if (lane == 31) swt[wid] = sv;
        __syncthreads();
        if (wid == 0) {
            int w = swt[lane];
            #pragma unroll
            for (int o = 1; o < 32; o <<= 1) {
                int t = __shfl_up_sync(0xffffffffu, w, o);
                if (lane >= o) w += t;
            }
            swt[lane] = w;
        }
        __syncthreads();
        int off = (wid > 0) ? swt[wid - 1] : 0;
        int incl = carry + off + sv;
        if (i < NN) rs[i + 1] = incl;
        int total = swt[31];
        __syncthreads();
        if (tid == 0) carry += total;
        __syncthreads();
    }
    // fused: dinv
    for (int i = tid; i < NN; i += 1024)
        g_dinv[br][i] = rsqrtf((float)deg[i]);
}

// ---------------- launch 3: CSR scatter (both branches) ----------------
__global__ void k_scatter(const int* __restrict__ ei_a, const int* __restrict__ ei_b) {
    int idx = blockIdx.x * blockDim.x + threadIdx.x;
    if (idx >= 2 * TOT) return;
    int br = idx >= TOT;
    int t  = idx - br * TOT;
    const int* ei = br ? ei_b : ei_a;
    int s, d;
    if (t < NE) { s = ei[t]; d = ei[NE + t]; }
    else        { s = d = t - NE; }
    int pos = g_rs[br][d] + atomicAdd(&g_cnt[br][d], 1);
    g_col[br][pos] = s;
}

// ------- launch 4: GAT linear h = x@W, alpha_s/d (both branches) -------
__global__ void __launch_bounds__(256) k_gath(
    const float* __restrict__ x_a, const float* __restrict__ x_b,
    const float* __restrict__ Wg,
    const float* __restrict__ asr, const float* __restrict__ adr)
{
    __shared__ float sW[9 * UF];
    __shared__ float sas[UF], sad[UF];
    for (int i = threadIdx.x; i < 9 * UF; i += 256) sW[i] = Wg[i];
    if (threadIdx.x < UF) { sas[threadIdx.x] = asr[threadIdx.x]; sad[threadIdx.x] = adr[threadIdx.x]; }
    __syncthreads();
    int gw   = (blockIdx.x * 256 + threadIdx.x) >> 5;
    int lane = threadIdx.x & 31;
    if (gw >= 2 * NN) return;
    int br   = gw >= NN;
    int node = gw - br * NN;
    const float* x = br ? x_b : x_a;
    float xr[9];
    #pragma unroll
    for (int k = 0; k < 9; k++) xr[k] = __ldg(&x[node * 9 + k]);
    int f0 = 2 * lane;
    float h0 = 0.f, h1 = 0.f;
    #pragma unroll
    for (int k = 0; k < 9; k++) {
        h0 = fmaf(xr[k], sW[k * UF + f0],     h0);
        h1 = fmaf(xr[k], sW[k * UF + f0 + 1], h1);
    }
    *(float2*)&g_x[br][0][node * UF + f0] = make_float2(h0, h1);
    float ps = fmaf(h0, sas[f0], h1 * sas[f0 + 1]);
    float pd = fmaf(h0, sad[f0], h1 * sad[f0 + 1]);
    ps = warp_sum(ps);
    pd = warp_sum(pd);
    if (lane == 0) { g_als[br][node] = ps; g_ald[br][node] = pd; }
}

// ------- launch 5: GAT aggregate + tanh + (x@W_gcn0), both branches -------
__global__ void __launch_bounds__(256) k_gat_agg(
    const float* __restrict__ bgat, const float* __restrict__ Wn)
{
    __shared__ float sW[UF * UF];
    for (int i = threadIdx.x; i < UF * UF; i += 256) sW[i] = Wn[i];
    __syncthreads();
    int half = gridDim.x >> 1;
    int br   = blockIdx.x >= half;
    int blk  = blockIdx.x - br * half;
    int lane = threadIdx.x & 31;
    int wid  = blk * 8 + (threadIdx.x >> 5);
    int nw   = half * 8;
    const int*   __restrict__ rs   = g_rs[br];
    const int*   __restrict__ colb = g_col[br];
    const float* __restrict__ als  = g_als[br];
    const float* __restrict__ hin  = g_x[br][0];
    float*       __restrict__ ew   = g_ew[br];
    float*       __restrict__ outp = g_x[br][1];
    float bg0 = __ldg(&bgat[2 * lane]);
    float bg1 = __ldg(&bgat[2 * lane + 1]);

    for (int node = wid; node < NN; node += nw) {
        int beg = rs[node], end = rs[node + 1];
        float ad = g_ald[br][node];
        // pass 1: compute edge logits, cache them, segment max
        float m = -3.0e38f;
        for (int j = beg + lane; j < end; j += 32) {
            float e = __ldg(&als[colb[j]]) + ad;
            e = e > 0.f ? e : 0.2f * e;
            ew[j] = e;
            m = fmaxf(m, e);
        }
        m = warp_max(m);
        // pass 2: joint-edge gather; ex/den uniform across lanes (no shfl)
        float a0 = 0.f, a1 = 0.f, den = 0.f;
        #pragma unroll 4
        for (int j = beg; j < end; j++) {
            int   s  = __ldg(&colb[j]);          // broadcast
            float ex = __expf(__ldg(&ew[j]) - m); // broadcast
            den += ex;
            float2 hv = *(const float2*)&hin[s * UF + 2 * lane];
            a0 = fmaf(ex, hv.x, a0);
            a1 = fmaf(ex, hv.y, a1);
        }
        float inv = __fdividef(1.f, den);
        float y0 = tanhf(fmaf(a0, inv, bg0));
        float y1 = tanhf(fmaf(a1, inv, bg1));
        // fused transform by W_gcn[0]
        float o0 = 0.f, o1 = 0.f;
        #pragma unroll
        for (int k = 0; k < UF; k++) {
            float yk = __shfl_sync(0xffffffffu, (k & 1) ? y1 : y0, k >> 1);
            float2 wv = *(const float2*)&sW[k * UF + 2 * lane];
            o0 = fmaf(yk, wv.x, o0);
            o1 = fmaf(yk, wv.y, o1);
        }
        *(float2*)&outp[node * UF + 2 * lane] = make_float2(o0, o1);
    }
}

// ------- launch 6: GCN aggregate + tanh + (x@W_gcn1), both branches -------
__global__ void __launch_bounds__(256) k_gcn_agg(
    const float* __restrict__ bg, const float* __restrict__ Wn)
{
    __shared__ float sW[UF * UF];
    for (int i = threadIdx.x; i < UF * UF; i += 256) sW[i] = Wn[i];
    __syncthreads();
    int half = gridDim.x >> 1;
    int br   = blockIdx.x >= half;
    int blk  = blockIdx.x - br * half;
    int lane = threadIdx.x & 31;
    int wid  = blk * 8 + (threadIdx.x >> 5);
    int nw   = half * 8;
    const int*   __restrict__ rs   = g_rs[br];
    const int*   __restrict__ colb = g_col[br];
    const float* __restrict__ dinv = g_dinv[br];
    const float* __restrict__ hin  = g_x[br][1];
    float*       __restrict__ outp = g_x[br][0];
    float bg0 = __ldg(&bg[2 * lane]);
    float bg1 = __ldg(&bg[2 * lane + 1]);

    for (int node = wid; node < NN; node += nw) {
        int beg = rs[node], end = rs[node + 1];
        float di = dinv[node];
        float a0 = 0.f, a1 = 0.f;
        #pragma unroll 4
        for (int j = beg; j < end; j++) {
            int   s = __ldg(&colb[j]);   // broadcast
            float w = __ldg(&dinv[s]);   // broadcast
            float2 hv = *(const float2*)&hin[s * UF + 2 * lane];
            a0 = fmaf(w, hv.x, a0);
            a1 = fmaf(w, hv.y, a1);
        }
        float y0 = tanhf(fmaf(a0, di, bg0));
        float y1 = tanhf(fmaf(a1, di, bg1));
        float o0 = 0.f, o1 = 0.f;
        #pragma unroll
        for (int k = 0; k < UF; k++) {
            float yk = __shfl_sync(0xffffffffu, (k & 1) ? y1 : y0, k >> 1);
            float2 wv = *(const float2*)&sW[k * UF + 2 * lane];
            o0 = fmaf(yk, wv.x, o0);
            o1 = fmaf(yk, wv.y, o1);
        }
        *(float2*)&outp[node * UF + 2 * lane] = make_float2(o0, o1);
    }
}

// -- launch 7: GCN2 aggregate + tanh + full MLP + pool partial, both branches --
__global__ void __launch_bounds__(256) k_final_node(
    const float* __restrict__ bg,
    const float* __restrict__ W1, const float* __restrict__ b1,
    const float* __restrict__ W2, const float* __restrict__ b2,
    const float* __restrict__ W3, const float* __restrict__ b3,
    const int* __restrict__ ba, const int* __restrict__ bb)
{
    __shared__ float sW1[UF * UF];
    __shared__ float sW2[UF * 32];
    __shared__ float sb1[UF], sb2[32], sW3[32];
    __shared__ float sb3;
    for (int i = threadIdx.x; i < UF * UF; i += 256) sW1[i] = W1[i];
    for (int i = threadIdx.x; i < UF * 32; i += 256) sW2[i] = W2[i];
    if (threadIdx.x < UF) sb1[threadIdx.x] = b1[threadIdx.x];
    if (threadIdx.x < 32) { sb2[threadIdx.x] = b2[threadIdx.x]; sW3[threadIdx.x] = W3[threadIdx.x]; }
    if (threadIdx.x == 0) sb3 = b3[0];
    __syncthreads();

    int half = gridDim.x >> 1;
    int br   = blockIdx.x >= half;
    int blk  = blockIdx.x - br * half;
    int lane = threadIdx.x & 31;
    int wid  = blk * 8 + (threadIdx.x >> 5);
    int nw   = half * 8;
    const int*   __restrict__ rs    = g_rs[br];
    const int*   __restrict__ colb  = g_col[br];
    const float* __restrict__ dinv  = g_dinv[br];
    const float* __restrict__ hin   = g_x[br][0];
    const int*   __restrict__ batch = br ? bb : ba;
    float* __restrict__ poolS = g_poolS[br];
    float bg0 = __ldg(&bg[2 * lane]);
    float bg1 = __ldg(&bg[2 * lane + 1]);

    for (int node = wid; node < NN; node += nw) {
        int beg = rs[node], end = rs[node + 1];
        float di = dinv[node];
        float a0 = 0.f, a1 = 0.f;
        #pragma unroll 4
        for (int j = beg; j < end; j++) {
            int   s = __ldg(&colb[j]);
            float w = __ldg(&dinv[s]);
            float2 hv = *(const float2*)&hin[s * UF + 2 * lane];
            a0 = fmaf(w, hv.x, a0);
            a1 = fmaf(w, hv.y, a1);
        }
        float y0 = tanhf(fmaf(a0, di, bg0));
        float y1 = tanhf(fmaf(a1, di, bg1));
        // MLP layer 1: 64 -> 64, tanh
        float o0 = sb1[2 * lane], o1 = sb1[2 * lane + 1];
        #pragma unroll
        for (int k = 0; k < UF; k++) {
            float yk = __shfl_sync(0xffffffffu, (k & 1) ? y1 : y0, k >> 1);
            float2 wv = *(const float2*)&sW1[k * UF + 2 * lane];
            o0 = fmaf(yk, wv.x, o0);
            o1 = fmaf(yk, wv.y, o1);
        }
        o0 = tanhf(o0);
        o1 = tanhf(o1);
        // MLP layer 2: 64 -> 32, tanh (one output per lane)
        float z = sb2[lane];
        #pragma unroll
        for (int k = 0; k < UF; k++) {
            float ok = __shfl_sync(0xffffffffu, (k & 1) ? o1 : o0, k >> 1);
            z = fmaf(ok, sW2[k * 32 + lane], z);
        }
        z = tanhf(z);
        // MLP layer 3: 32 -> 1
        float p = warp_sum(z * sW3[lane]);
        if (lane == 0) atomicAdd(&poolS[batch[node]], p + sb3);
    }
}

// ---------------- launch 8: mean-pool (counts by binary search) + sigmoid ----------------
static __device__ __forceinline__ int lb(const int* __restrict__ b, int v) {
    int lo = 0, hi = NN;
    while (lo < hi) {
        int mid = (lo + hi) >> 1;
        if (b[mid] < v) lo = mid + 1; else hi = mid;
    }
    return lo;
}

__global__ void k_out(float* __restrict__ out,
                      const int* __restrict__ ba, const int* __restrict__ bb) {
    int g = blockIdx.x * blockDim.x + threadIdx.x;
    if (g >= NG) return;
    float ca = (float)(lb(ba, g + 1) - lb(ba, g));
    float cb = (float)(lb(bb, g + 1) - lb(bb, g));
    float ua = g_poolS[0][g] / fmaxf(ca, 1.f);
    float ub = g_poolS[1][g] / fmaxf(cb, 1.f);
    out[g] = 1.f / (1.f + expf(-(ub - ua)));
}

// ---------------- launch ----------------
extern "C" void kernel_launch(void* const* d_in, const int* in_sizes, int n_in,
                              void* d_out, int out_size)
{
    const float* x_a   = (const float*)d_in[0];
    const float* x_b   = (const float*)d_in[1];
    const int*   ei_a  = (const int*)d_in[2];
    const int*   ei_b  = (const int*)d_in[3];
    const int*   ba    = (const int*)d_in[4];
    const int*   bb    = (const int*)d_in[5];
    const float* W_gat = (const float*)d_in[6];
    const float* a_src = (const float*)d_in[7];
    const float* a_dst = (const float*)d_in[8];
    const float* b_gat = (const float*)d_in[9];
    const float* W_gcn = (const float*)d_in[10];
    const float* b_gcn = (const float*)d_in[11];
    const float* W1    = (const float*)d_in[12];
    const float* b1    = (const float*)d_in[13];
    const float* W2    = (const float*)d_in[14];
    const float* b2    = (const float*)d_in[15];
    const float* W3    = (const float*)d_in[16];
    const float* b3    = (const float*)d_in[17];
    float* out = (float*)d_out;

    const int NB2 = 2368;  // 2 x (148 SMs x 8 blocks)

    k_init<<<(2 * NN + 255) / 256, 256>>>();
    k_hist<<<(2 * NE + 255) / 256, 256>>>(ei_a, ei_b);
    k_scan<<<2, 1024>>>();
    k_scatter<<<(2 * TOT + 255) / 256, 256>>>(ei_a, ei_b);
    k_gath<<<(2 * NN * 32 + 255) / 256, 256>>>(x_a, x_b, W_gat, a_src, a_dst);
    k_gat_agg<<<NB2, 256>>>(b_gat, W_gcn);
    k_gcn_agg<<<NB2, 256>>>(b_gcn, W_gcn + UF * UF);
    k_final_node<<<NB2, 256>>>(b_gcn + UF, W1, b1, W2, b2, W3, b3, ba, bb);
    k_out<<<(NG + 255) / 256, 256>>>(out, ba, bb);
}

// round 13
// speedup vs baseline: 1.6642x; 1.5000x over previous
#include <cuda_runtime.h>
#include <cuda_fp16.h>
#include <math.h>

#define NN 50000
#define NE 800000
#define NG 512
#define UF 64
#define TOT (NE + NN)
#define NTILES ((2 * NN) / 16)   // 6250 mma tiles of 16 nodes

// ---------------- device scratch (no allocs allowed) ----------------
__device__ int    g_rs[2][NN + 1];      // CSR row starts (by dst)
__device__ int    g_deg[2][NN];         // in-degree incl self loop
__device__ int    g_cnt[2][NN];         // scatter cursors
__device__ float2 g_ce[2][TOT];         // .x = col bits, .y = GAT logit/exp
__device__ float  g_dinv[2][NN];        // rsqrt(deg), flat = [2*NN]
__device__ float  g_als[2][NN];         // alpha_src per node
__device__ float  g_ald[2][NN];         // alpha_dst per node
__device__ float  g_f0[2 * NN * UF];    // feature ping (fp32)
__device__ float  g_f1[2 * NN * UF];    // feature pong (fp32)
__device__ float  g_poolS[2][NG];

static __device__ __forceinline__ float warp_sum(float v) {
    #pragma unroll
    for (int o = 16; o; o >>= 1) v += __shfl_xor_sync(0xffffffffu, v, o);
    return v;
}
static __device__ __forceinline__ float warp_max(float v) {
    #pragma unroll
    for (int o = 16; o; o >>= 1) v = fmaxf(v, __shfl_xor_sync(0xffffffffu, v, o));
    return v;
}
static __device__ __forceinline__ float tfast(float x) {
    return 1.f - __fdividef(2.f, __expf(2.f * x) + 1.f);
}
// split fp32 pair into fp16 hi + fp16 residual lo (packed half2 as uint)
static __device__ __forceinline__ void split2(float x, float y, unsigned& hi, unsigned& lo) {
    __half2 h = __floats2half2_rn(x, y);
    float2 hf = __half22float2(h);
    __half2 l = __floats2half2_rn(x - hf.x, y - hf.y);
    hi = *reinterpret_cast<unsigned*>(&h);
    lo = *reinterpret_cast<unsigned*>(&l);
}
static __device__ __forceinline__ void mma16816(
    float& c0, float& c1, float& c2, float& c3,
    unsigned a0, unsigned a1, unsigned a2, unsigned a3,
    unsigned b0, unsigned b1)
{
    asm volatile(
        "mma.sync.aligned.m16n8k16.row.col.f32.f16.f16.f32 "
        "{%0,%1,%2,%3},{%4,%5,%6,%7},{%8,%9},{%0,%1,%2,%3};"
        : "+f"(c0), "+f"(c1), "+f"(c2), "+f"(c3)
        : "r"(a0), "r"(a1), "r"(a2), "r"(a3), "r"(b0), "r"(b1));
}

// ---------------- launch 0: init ----------------
__global__ void k_init() {
    int i = blockIdx.x * blockDim.x + threadIdx.x;
    if (i < 2 * NN) {
        int br = i / NN, j = i % NN;
        g_deg[br][j] = 1;
        g_cnt[br][j] = 0;
    }
    if (i < 2 * NG) {
        int br = i / NG, j = i % NG;
        g_poolS[br][j] = 0.f;
    }
}

// ------- launch 1: hist (blocks [0,HB)) + GAT linear (blocks [HB,..)) -------
#define HB 6250   // (2*NE)/256
__global__ void __launch_bounds__(256) k_hist_gath(
    const int* __restrict__ ei_a, const int* __restrict__ ei_b,
    const float* __restrict__ x_a, const float* __restrict__ x_b,
    const float* __restrict__ Wg,
    const float* __restrict__ asr, const float* __restrict__ adr)
{
    __shared__ float sW[9 * UF];
    __shared__ float sas[UF], sad[UF];
    if (blockIdx.x < HB) {
        int idx = blockIdx.x * 256 + threadIdx.x;
        if (idx < 2 * NE) {
            int br = idx >= NE;
            int e  = idx - br * NE;
            const int* ei = br ? ei_b : ei_a;
            atomicAdd(&g_deg[br][ei[NE + e]], 1);
        }
        return;
    }
    for (int i = threadIdx.x; i < 9 * UF; i += 256) sW[i] = Wg[i];
    if (threadIdx.x < UF) { sas[threadIdx.x] = asr[threadIdx.x]; sad[threadIdx.x] = adr[threadIdx.x]; }
    __syncthreads();
    int gw   = ((blockIdx.x - HB) * 256 + threadIdx.x) >> 5;   // flat node 0..2*NN-1
    int lane = threadIdx.x & 31;
    if (gw >= 2 * NN) return;
    int br   = gw >= NN;
    int node = gw - br * NN;
    const float* x = br ? x_b : x_a;
    float xr[9];
    #pragma unroll
    for (int k = 0; k < 9; k++) xr[k] = __ldg(&x[node * 9 + k]);
    int f0 = 2 * lane;
    float h0 = 0.f, h1 = 0.f;
    #pragma unroll
    for (int k = 0; k < 9; k++) {
        h0 = fmaf(xr[k], sW[k * UF + f0],     h0);
        h1 = fmaf(xr[k], sW[k * UF + f0 + 1], h1);
    }
    ((float2*)g_f0)[gw * 32 + lane] = make_float2(h0, h1);
    float ps = fmaf(h0, sas[f0], h1 * sas[f0 + 1]);
    float pd = fmaf(h0, sad[f0], h1 * sad[f0 + 1]);
    ps = warp_sum(ps);
    pd = warp_sum(pd);
    if (lane == 0) { g_als[br][node] = ps; g_ald[br][node] = pd; }
}

// ---------------- launch 2: prefix scan + dinv (1 block per branch) ----------------
__global__ void k_scan() {
    int br = blockIdx.x;
    int* deg = g_deg[br];
    int* rs  = g_rs[br];
    __shared__ int swt[32];
    __shared__ int carry;
    int tid = threadIdx.x, lane = tid & 31, wid = tid >> 5;
    if (tid == 0) { carry = 0; rs[0] = 0; }
    __syncthreads();
    for (int base = 0; base < NN; base += 1024) {
        int i = base + tid;
        int v = (i < NN) ? deg[i] : 0;
        int sv = v;
        #pragma unroll
        for (int o = 1; o < 32; o <<= 1) {
            int t = __shfl_up_sync(0xffffffffu, sv, o);
            if (lane >= o) sv += t;
        }
        if (lane == 31) swt[wid] = sv;
        __syncthreads();
        if (wid == 0) {
            int w = swt[lane];
            #pragma unroll
            for (int o = 1; o < 32; o <<= 1) {
                int t = __shfl_up_sync(0xffffffffu, w, o);
                if (lane >= o) w += t;
            }
            swt[lane] = w;
        }
        __syncthreads();
        int off = (wid > 0) ? swt[wid - 1] : 0;
        int incl = carry + off + sv;
        if (i < NN) rs[i + 1] = incl;
        int total = swt[31];
        __syncthreads();
        if (tid == 0) carry += total;
        __syncthreads();
    }
    for (int i = tid; i < NN; i += 1024)
        g_dinv[br][i] = rsqrtf((float)deg[i]);
}

// ---------------- launch 3: CSR scatter (both branches) ----------------
__global__ void k_scatter(const int* __restrict__ ei_a, const int* __restrict__ ei_b) {
    int idx = blockIdx.x * blockDim.x + threadIdx.x;
    if (idx >= 2 * TOT) return;
    int br = idx >= TOT;
    int t  = idx - br * TOT;
    const int* ei = br ? ei_b : ei_a;
    int s, d;
    if (t < NE) { s = ei[t]; d = ei[NE + t]; }
    else        { s = d = t - NE; }
    int pos = g_rs[br][d] + atomicAdd(&g_cnt[br][d], 1);
    g_ce[br][pos].x = __int_as_float(s);
}

// ------- launch 4: GAT aggregate + tanh -> y1 (fp32), both branches -------
__global__ void __launch_bounds__(256) k_gat_agg(const float* __restrict__ bgat)
{
    int half = gridDim.x >> 1;
    int br   = blockIdx.x >= half;
    int blk  = blockIdx.x - br * half;
    int lane = threadIdx.x & 31;
    int wid  = blk * 8 + (threadIdx.x >> 5);
    int nw   = half * 8;
    const int*    __restrict__ rs  = g_rs[br];
    float2*       __restrict__ ce  = g_ce[br];
    const float*  __restrict__ als = g_als[br];
    const float2* hin  = (const float2*)g_f0 + (size_t)br * NN * 32;
    float2*       outp = (float2*)g_f1 + (size_t)br * NN * 32;
    float bg0 = __ldg(&bgat[2 * lane]);
    float bg1 = __ldg(&bgat[2 * lane + 1]);

    for (int node = wid; node < NN; node += nw) {
        int beg = rs[node], end = rs[node + 1];
        float ad = g_ald[br][node];
        // pass 1: logits + segment max (lane-strided)
        float m = -3.0e38f;
        for (int j = beg + lane; j < end; j += 32) {
            int s = __float_as_int(ce[j].x);
            float e = __ldg(&als[s]) + ad;
            e = e > 0.f ? e : 0.2f * e;
            ce[j].y = e;
            m = fmaxf(m, e);
        }
        m = warp_max(m);
        // pass 1.5: exp once per edge (same lanes), accumulate denom
        float den = 0.f;
        for (int j = beg + lane; j < end; j += 32) {
            float ex = __expf(ce[j].y - m);
            ce[j].y = ex;
            den += ex;
        }
        den = warp_sum(den);
        __syncwarp();                       // make lane-strided ce.y writes visible
        // pass 2: weighted gather (joint edges, fp32 rows)
        float a0 = 0.f, a1 = 0.f, p0 = 0.f, p1 = 0.f;
        int j = beg;
        for (; j + 1 < end; j += 2) {
            float2 c0 = ce[j], c1 = ce[j + 1];
            int s0 = __float_as_int(c0.x), s1 = __float_as_int(c1.x);
            float2 f0v = hin[s0 * 32 + lane];
            float2 f1v = hin[s1 * 32 + lane];
            a0 = fmaf(c0.y, f0v.x, a0);  a1 = fmaf(c0.y, f0v.y, a1);
            p0 = fmaf(c1.y, f1v.x, p0);  p1 = fmaf(c1.y, f1v.y, p1);
        }
        if (j < end) {
            float2 c0 = ce[j];
            int s0 = __float_as_int(c0.x);
            float2 f0v = hin[s0 * 32 + lane];
            a0 = fmaf(c0.y, f0v.x, a0);  a1 = fmaf(c0.y, f0v.y, a1);
        }
        a0 += p0; a1 += p1;
        float inv = __fdividef(1.f, den);
        float y0 = tfast(fmaf(a0, inv, bg0));
        float y1 = tfast(fmaf(a1, inv, bg1));
        outp[node * 32 + lane] = make_float2(y0, y1);
    }
}

// ------- mma GEMM (split fp16 ~ fp32 accuracy): g_f0 = (g_f1 @ W) * dinv -------
__global__ void __launch_bounds__(256) k_gemm(const float* __restrict__ Wf)
{
    __shared__ __align__(4) __half sWh[64 * 72];
    __shared__ __align__(4) __half sWl[64 * 72];
    for (int i = threadIdx.x; i < 64 * 64; i += 256) {
        int k = i >> 6, n = i & 63;
        float w = Wf[i];
        __half h = __float2half_rn(w);
        sWh[n * 72 + k] = h;
        sWl[n * 72 + k] = __float2half_rn(w - __half2float(h));
    }
    __syncthreads();
    int t = blockIdx.x * 8 + (threadIdx.x >> 5);
    if (t >= NTILES) return;
    int lane = threadIdx.x & 31, q = lane & 3, r = lane >> 2;
    int n0 = t * 16;
    const float* Ap = g_f1;
    unsigned ah[4][4], al[4][4];
    #pragma unroll
    for (int kt = 0; kt < 4; kt++) {
        int b0 = (n0 + r) * 64 + kt * 16 + 2 * q;
        int b1 = (n0 + r + 8) * 64 + kt * 16 + 2 * q;
        split2(Ap[b0],     Ap[b0 + 1], ah[kt][0], al[kt][0]);
        split2(Ap[b1],     Ap[b1 + 1], ah[kt][1], al[kt][1]);
        split2(Ap[b0 + 8], Ap[b0 + 9], ah[kt][2], al[kt][2]);
        split2(Ap[b1 + 8], Ap[b1 + 9], ah[kt][3], al[kt][3]);
    }
    const float* dv = (const float*)g_dinv;
    float d0 = dv[n0 + r], d1 = dv[n0 + r + 8];
    float2* Op = (float2*)g_f0;
    const unsigned* Bh = (const unsigned*)sWh;
    const unsigned* Bl = (const unsigned*)sWl;
    #pragma unroll
    for (int nt = 0; nt < 8; nt++) {
        float c0 = 0.f, c1 = 0.f, c2 = 0.f, c3 = 0.f;
        #pragma unroll
        for (int kt = 0; kt < 4; kt++) {
            int bi = (nt * 8 + r) * 36 + kt * 8 + q;
            unsigned bh0 = Bh[bi], bh1 = Bh[bi + 4];
            unsigned bl0 = Bl[bi], bl1 = Bl[bi + 4];
            mma16816(c0, c1, c2, c3, ah[kt][0], ah[kt][1], ah[kt][2], ah[kt][3], bh0, bh1);
            mma16816(c0, c1, c2, c3, ah[kt][0], ah[kt][1], ah[kt][2], ah[kt][3], bl0, bl1);
            mma16816(c0, c1, c2, c3, al[kt][0], al[kt][1], al[kt][2], al[kt][3], bh0, bh1);
        }
        Op[(n0 + r) * 32 + nt * 4 + q]     = make_float2(c0 * d0, c1 * d0);
        Op[(n0 + r + 8) * 32 + nt * 4 + q] = make_float2(c2 * d1, c3 * d1);
    }
}

// ------- GCN aggregate: g_f1 = tanh(di * sum(g_f0[src]) + b), both branches -------
__global__ void __launch_bounds__(256) k_gcn_agg(const float* __restrict__ bg)
{
    int half = gridDim.x >> 1;
    int br   = blockIdx.x >= half;
    int blk  = blockIdx.x - br * half;
    int lane = threadIdx.x & 31;
    int wid  = blk * 8 + (threadIdx.x >> 5);
    int nw   = half * 8;
    const int*   __restrict__ rs   = g_rs[br];
    const float* __restrict__ cx   = (const float*)g_ce[br];   // stride-2 col stream
    const float* __restrict__ dinv = g_dinv[br];
    const float2* hin  = (const float2*)g_f0 + (size_t)br * NN * 32;
    float2*       outp = (float2*)g_f1 + (size_t)br * NN * 32;
    float bg0 = __ldg(&bg[2 * lane]);
    float bg1 = __ldg(&bg[2 * lane + 1]);

    for (int node = wid; node < NN; node += nw) {
        int beg = rs[node], end = rs[node + 1];
        float di = dinv[node];
        float a0 = 0.f, a1 = 0.f, p0 = 0.f, p1 = 0.f;
        int j = beg;
        for (; j + 1 < end; j += 2) {
            int s0 = __float_as_int(__ldg(&cx[2 * j]));
            int s1 = __float_as_int(__ldg(&cx[2 * j + 2]));
            float2 f0v = hin[s0 * 32 + lane];
            float2 f1v = hin[s1 * 32 + lane];
            a0 += f0v.x;  a1 += f0v.y;
            p0 += f1v.x;  p1 += f1v.y;
        }
        if (j < end) {
            int s0 = __float_as_int(__ldg(&cx[2 * j]));
            float2 f0v = hin[s0 * 32 + lane];
            a0 += f0v.x;  a1 += f0v.y;
        }
        a0 += p0; a1 += p1;
        float y0 = tfast(fmaf(a0, di, bg0));
        float y1 = tfast(fmaf(a1, di, bg1));
        outp[node * 32 + lane] = make_float2(y0, y1);
    }
}

// ------- mma MLP (split fp16): g_f1 -> tanh(W1)+b1 -> tanh(W2)+b2 -> W3+b3 -> pool -------
__global__ void __launch_bounds__(256) k_mlp(
    const float* __restrict__ W1, const float* __restrict__ b1,
    const float* __restrict__ W2, const float* __restrict__ b2,
    const float* __restrict__ W3, const float* __restrict__ b3,
    const int* __restrict__ ba, const int* __restrict__ bb)
{
    __shared__ __align__(4) __half sW1h[64 * 72];
    __shared__ __align__(4) __half sW1l[64 * 72];
    __shared__ __align__(4) __half sW2h[32 * 72];
    __shared__ __align__(4) __half sW2l[32 * 72];
    __shared__ float sb1[64], sb2[32], sw3[32];
    __shared__ float sb3;
    for (int i = threadIdx.x; i < 64 * 64; i += 256) {
        int k = i >> 6, n = i & 63;
        float w = W1[i];
        __half h = __float2half_rn(w);
        sW1h[n * 72 + k] = h;
        sW1l[n * 72 + k] = __float2half_rn(w - __half2float(h));
    }
    for (int i = threadIdx.x; i < 64 * 32; i += 256) {
        int k = i >> 5, n = i & 31;
        float w = W2[i];
        __half h = __float2half_rn(w);
        sW2h[n * 72 + k] = h;
        sW2l[n * 72 + k] = __float2half_rn(w - __half2float(h));
    }
    if (threadIdx.x < 64) sb1[threadIdx.x] = b1[threadIdx.x];
    if (threadIdx.x < 32) { sb2[threadIdx.x] = b2[threadIdx.x]; sw3[threadIdx.x] = W3[threadIdx.x]; }
    if (threadIdx.x == 0) sb3 = b3[0];
    __syncthreads();
    int t = blockIdx.x * 8 + (threadIdx.x >> 5);
    if (t >= NTILES) return;
    int lane = threadIdx.x & 31, q = lane & 3, r = lane >> 2;
    int n0 = t * 16;
    const float* Ap = g_f1;
    unsigned ah[4][4], al[4][4];
    #pragma unroll
    for (int kt = 0; kt < 4; kt++) {
        int o0 = (n0 + r) * 64 + kt * 16 + 2 * q;
        int o1 = (n0 + r + 8) * 64 + kt * 16 + 2 * q;
        split2(Ap[o0],     Ap[o0 + 1], ah[kt][0], al[kt][0]);
        split2(Ap[o1],     Ap[o1 + 1], ah[kt][1], al[kt][1]);
        split2(Ap[o0 + 8], Ap[o0 + 9], ah[kt][2], al[kt][2]);
        split2(Ap[o1 + 8], Ap[o1 + 9], ah[kt][3], al[kt][3]);
    }
    const unsigned* B1h = (const unsigned*)sW1h;
    const unsigned* B1l = (const unsigned*)sW1l;
    const unsigned* B2h = (const unsigned*)sW2h;
    const unsigned* B2l = (const unsigned*)sW2l;
    // GEMM1: [16x64] @ [64x64], bias + tanh
    float c1v[8][4];
    #pragma unroll
    for (int nt = 0; nt < 8; nt++) {
        float c0 = 0.f, c1 = 0.f, c2 = 0.f, c3 = 0.f;
        #pragma unroll
        for (int kt = 0; kt < 4; kt++) {
            int bi = (nt * 8 + r) * 36 + kt * 8 + q;
            unsigned bh0 = B1h[bi], bh1 = B1h[bi + 4];
            unsigned bl0 = B1l[bi], bl1 = B1l[bi + 4];
            mma16816(c0, c1, c2, c3, ah[kt][0], ah[kt][1], ah[kt][2], ah[kt][3], bh0, bh1);
            mma16816(c0, c1, c2, c3, ah[kt][0], ah[kt][1], ah[kt][2], ah[kt][3], bl0, bl1);
            mma16816(c0, c1, c2, c3, al[kt][0], al[kt][1], al[kt][2], al[kt][3], bh0, bh1);
        }
        int col = nt * 8 + q * 2;
        c1v[nt][0] = tfast(c0 + sb1[col]);
        c1v[nt][1] = tfast(c1 + sb1[col + 1]);
        c1v[nt][2] = tfast(c2 + sb1[col]);
        c1v[nt][3] = tfast(c3 + sb1[col + 1]);
    }
    // Re-fragment tanh(C1) as split A2 (register-local)
    unsigned a2h[4][4], a2l[4][4];
    #pragma unroll
    for (int kt = 0; kt < 4; kt++) {
        split2(c1v[2 * kt][0],     c1v[2 * kt][1],     a2h[kt][0], a2l[kt][0]);
        split2(c1v[2 * kt][2],     c1v[2 * kt][3],     a2h[kt][1], a2l[kt][1]);
        split2(c1v[2 * kt + 1][0], c1v[2 * kt + 1][1], a2h[kt][2], a2l[kt][2]);
        split2(c1v[2 * kt + 1][2], c1v[2 * kt + 1][3], a2h[kt][3], a2l[kt][3]);
    }
    // GEMM2: [16x64] @ [64x32], tanh, dot with w3
    float p0 = 0.f, p1 = 0.f;
    #pragma unroll
    for (int nt = 0; nt < 4; nt++) {
        float c0 = 0.f, c1 = 0.f, c2 = 0.f, c3 = 0.f;
        #pragma unroll
        for (int kt = 0; kt < 4; kt++) {
            int bi = (nt * 8 + r) * 36 + kt * 8 + q;
            unsigned bh0 = B2h[bi], bh1 = B2h[bi + 4];
            unsigned bl0 = B2l[bi], bl1 = B2l[bi + 4];
            mma16816(c0, c1, c2, c3, a2h[kt][0], a2h[kt][1], a2h[kt][2], a2h[kt][3], bh0, bh1);
            mma16816(c0, c1, c2, c3, a2h[kt][0], a2h[kt][1], a2h[kt][2], a2h[kt][3], bl0, bl1);
            mma16816(c0, c1, c2, c3, a2l[kt][0], a2l[kt][1], a2l[kt][2], a2l[kt][3], bh0, bh1);
        }
        int col = nt * 8 + q * 2;
        float w0 = sw3[col], w1 = sw3[col + 1];
        p0 = fmaf(tfast(c0 + sb2[col]), w0, p0);
        p0 = fmaf(tfast(c1 + sb2[col + 1]), w1, p0);
        p1 = fmaf(tfast(c2 + sb2[col]), w0, p1);
        p1 = fmaf(tfast(c3 + sb2[col + 1]), w1, p1);
    }
    // reduce across the quad (lanes sharing the same rows)
    p0 += __shfl_xor_sync(0xffffffffu, p0, 1);
    p0 += __shfl_xor_sync(0xffffffffu, p0, 2);
    p1 += __shfl_xor_sync(0xffffffffu, p1, 1);
    p1 += __shfl_xor_sync(0xffffffffu, p1, 2);
    if (q == 0) {
        int br = n0 >= NN;
        int nl = n0 - br * NN;
        const int* batch = br ? bb : ba;
        float* pool = g_poolS[br];
        atomicAdd(&pool[batch[nl + r]],     p0 + sb3);
        atomicAdd(&pool[batch[nl + r + 8]], p1 + sb3);
    }
}

// ---------------- mean-pool (counts by binary search) + sigmoid ----------------
static __device__ __forceinline__ int lb(const int* __restrict__ b, int v) {
    int lo = 0, hi = NN;
    while (lo < hi) {
        int mid = (lo + hi) >> 1;
        if (b[mid] < v) lo = mid + 1; else hi = mid;
    }
    return lo;
}

__global__ void k_out(float* __restrict__ out,
                      const int* __restrict__ ba, const int* __restrict__ bb) {
    int g = blockIdx.x * blockDim.x + threadIdx.x;
    if (g >= NG) return;
    float ca = (float)(lb(ba, g + 1) - lb(ba, g));
    float cb = (float)(lb(bb, g + 1) - lb(bb, g));
    float ua = g_poolS[0][g] / fmaxf(ca, 1.f);
    float ub = g_poolS[1][g] / fmaxf(cb, 1.f);
    out[g] = 1.f / (1.f + expf(-(ub - ua)));
}

// ---------------- launch ----------------
extern "C" void kernel_launch(void* const* d_in, const int* in_sizes, int n_in,
                              void* d_out, int out_size)
{
    const float* x_a   = (const float*)d_in[0];
    const float* x_b   = (const float*)d_in[1];
    const int*   ei_a  = (const int*)d_in[2];
    const int*   ei_b  = (const int*)d_in[3];
    const int*   ba    = (const int*)d_in[4];
    const int*   bb    = (const int*)d_in[5];
    const float* W_gat = (const float*)d_in[6];
    const float* a_src = (const float*)d_in[7];
    const float* a_dst = (const float*)d_in[8];
    const float* b_gat = (const float*)d_in[9];
    const float* W_gcn = (const float*)d_in[10];
    const float* b_gcn = (const float*)d_in[11];
    const float* W1    = (const float*)d_in[12];
    const float* b1    = (const float*)d_in[13];
    const float* W2    = (const float*)d_in[14];
    const float* b2    = (const float*)d_in[15];
    const float* W3    = (const float*)d_in[16];
    const float* b3    = (const float*)d_in[17];
    float* out = (float*)d_out;

    const int NB2 = 2368;               // 2 x 1184 blocks, 8 warps each
    const int GB  = (2 * NN) / 8;       // 12500 blocks for gath part
    const int MMB = (NTILES + 7) / 8;   // 782 blocks for mma kernels

    k_init<<<(2 * NN + 255) / 256, 256>>>();
    k_hist_gath<<<HB + GB, 256>>>(ei_a, ei_b, x_a, x_b, W_gat, a_src, a_dst);
    k_scan<<<2, 1024>>>();
    k_scatter<<<(2 * TOT + 255) / 256, 256>>>(ei_a, ei_b);
    k_gat_agg<<<NB2, 256>>>(b_gat);
    k_gemm<<<MMB, 256>>>(W_gcn);                 // f1 -> f0, * W_gcn[0], * dinv
    k_gcn_agg<<<NB2, 256>>>(b_gcn);              // f0 -> f1, + b_gcn[0]
    k_gemm<<<MMB, 256>>>(W_gcn + UF * UF);       // f1 -> f0, * W_gcn[1], * dinv
    k_gcn_agg<<<NB2, 256>>>(b_gcn + UF);         // f0 -> f1, + b_gcn[1]
    k_mlp<<<MMB, 256>>>(W1, b1, W2, b2, W3, b3, ba, bb);
    k_out<<<(NG + 255) / 256, 256>>>(out, ba, bb);
}